// round 1
// baseline (speedup 1.0000x reference)
#include <cuda_runtime.h>
#include <cuda_bf16.h>

// LightGCNConv: out = norm_dst ⊙ scatter_sum(dst, feature[src] * norm_src[src])
// feature: [N, 64] f32, src/dst: [E] i32, out: [N, 64] f32
//
// Pipeline (all on default stream, graph-capturable, allocation-free):
//   0) cudaMemsetAsync(d_out, 0)
//   1) zero degree scratch (__device__ globals)
//   2) count out-degree (src) and in-degree (dst) with int atomics
//   3) scatter: 16 threads/edge, float4 lanes, red.global.add.v4.f32
//   4) finalize: out *= rsqrt(max(in_deg,1))

#define MAX_NODES 100000
#define DFEAT 64
#define DVEC 16  // float4s per row

__device__ int g_outdeg[MAX_NODES];
__device__ int g_indeg[MAX_NODES];

__global__ void zero_deg_kernel(int n) {
    int i = blockIdx.x * blockDim.x + threadIdx.x;
    if (i < n) {
        g_outdeg[i] = 0;
        g_indeg[i] = 0;
    }
}

__global__ void count_deg_kernel(const int* __restrict__ src,
                                 const int* __restrict__ dst, int E) {
    int e = blockIdx.x * blockDim.x + threadIdx.x;
    if (e < E) {
        atomicAdd(&g_outdeg[src[e]], 1);
        atomicAdd(&g_indeg[dst[e]], 1);
    }
}

// 16 threads per edge; thread q owns float4 #q of the 64-float row.
__global__ void scatter_kernel(const float4* __restrict__ feat,
                               const int* __restrict__ src,
                               const int* __restrict__ dst,
                               float4* __restrict__ out, int E) {
    long long t = (long long)blockIdx.x * blockDim.x + threadIdx.x;
    int e = (int)(t >> 4);
    int q = (int)(t & 15);
    if (e >= E) return;

    int s = __ldg(&src[e]);
    int d = __ldg(&dst[e]);
    float rn = rsqrtf((float)max(g_outdeg[s], 1));

    float4 v = __ldg(&feat[(long long)s * DVEC + q]);
    v.x *= rn; v.y *= rn; v.z *= rn; v.w *= rn;

    float4* addr = &out[(long long)d * DVEC + q];
    asm volatile("red.global.add.v4.f32 [%0], {%1, %2, %3, %4};"
                 :: "l"(addr), "f"(v.x), "f"(v.y), "f"(v.z), "f"(v.w)
                 : "memory");
}

__global__ void finalize_kernel(float4* __restrict__ out, int n) {
    int i = blockIdx.x * blockDim.x + threadIdx.x;  // over n*16 float4s
    if (i >= n * DVEC) return;
    int node = i >> 4;
    float rn = rsqrtf((float)max(g_indeg[node], 1));
    float4 v = out[i];
    v.x *= rn; v.y *= rn; v.z *= rn; v.w *= rn;
    out[i] = v;
}

extern "C" void kernel_launch(void* const* d_in, const int* in_sizes, int n_in,
                              void* d_out, int out_size) {
    const float4* feat = (const float4*)d_in[0];
    const int*    src  = (const int*)d_in[1];
    const int*    dst  = (const int*)d_in[2];
    float4*       out  = (float4*)d_out;

    int N = in_sizes[0] / DFEAT;   // 100000
    int E = in_sizes[1];           // 1000000

    // 0) zero the accumulator (d_out is poisoned by the harness)
    cudaMemsetAsync(d_out, 0, (size_t)out_size * sizeof(float));

    // 1) zero degree scratch
    {
        int threads = 256;
        int blocks = (N + threads - 1) / threads;
        zero_deg_kernel<<<blocks, threads>>>(N);
    }

    // 2) degree counts
    {
        int threads = 256;
        int blocks = (E + threads - 1) / threads;
        count_deg_kernel<<<blocks, threads>>>(src, dst, E);
    }

    // 3) normalized gather + vector-red scatter
    {
        long long total = (long long)E * DVEC;
        int threads = 256;
        int blocks = (int)((total + threads - 1) / threads);
        scatter_kernel<<<blocks, threads>>>(feat, src, dst, out, E);
    }

    // 4) post-normalize by in-degree
    {
        int total = N * DVEC;
        int threads = 256;
        int blocks = (total + threads - 1) / threads;
        finalize_kernel<<<blocks, threads>>>(out, N);
    }
}